// round 1
// baseline (speedup 1.0000x reference)
#include <cuda_runtime.h>

#define NSEQ 2048
#define DH   64
#define NBH  32      // B*H = 2*16
#define QTILE 64
#define KTILE 64

static __device__ float g_m[NBH * NSEQ];
static __device__ float g_l[NBH * NSEQ];

__global__ __launch_bounds__(256) void qk_kernel(
    const float* __restrict__ q, const float* __restrict__ k,
    const int* __restrict__ mask, float* __restrict__ attn)
{
    __shared__ float QsT[DH][68];   // [d][qrow], padded for alignment/banks
    __shared__ float KsT[DH][68];   // [d][krow]
    __shared__ int   mq[QTILE];
    __shared__ int   mk[KTILE];

    const int qt  = blockIdx.x;
    const int bh  = blockIdx.y;
    const int b   = bh >> 4;
    const int tid = threadIdx.x;
    const int tx  = tid & 15;
    const int ty  = tid >> 4;
    const int r   = tid >> 2;          // 0..63 (row for cooperative loads)
    const int c0  = (tid & 3) * 16;    // 0,16,32,48

    // Load Q tile transposed: QsT[d][row]
    const float* qbase = q + ((size_t)bh * NSEQ + (size_t)qt * QTILE) * DH;
    #pragma unroll
    for (int c = 0; c < 16; c += 4) {
        float4 vq = *(const float4*)(qbase + r * DH + c0 + c);
        QsT[c0 + c + 0][r] = vq.x;
        QsT[c0 + c + 1][r] = vq.y;
        QsT[c0 + c + 2][r] = vq.z;
        QsT[c0 + c + 3][r] = vq.w;
    }
    if (tid < QTILE) mq[tid] = mask[b * NSEQ + qt * QTILE + tid];

    float* arow_base = attn + ((size_t)bh * NSEQ + (size_t)qt * QTILE) * NSEQ;

    for (int kt = 0; kt < NSEQ / KTILE; ++kt) {
        __syncthreads();
        const float* kbase = k + ((size_t)bh * NSEQ + (size_t)kt * KTILE) * DH;
        #pragma unroll
        for (int c = 0; c < 16; c += 4) {
            float4 vk = *(const float4*)(kbase + r * DH + c0 + c);
            KsT[c0 + c + 0][r] = vk.x;
            KsT[c0 + c + 1][r] = vk.y;
            KsT[c0 + c + 2][r] = vk.z;
            KsT[c0 + c + 3][r] = vk.w;
        }
        if (tid < KTILE) mk[tid] = mask[b * NSEQ + kt * KTILE + tid];
        __syncthreads();

        float acc[4][4];
        #pragma unroll
        for (int i = 0; i < 4; ++i)
            #pragma unroll
            for (int j = 0; j < 4; ++j) acc[i][j] = 0.f;

        #pragma unroll 8
        for (int d = 0; d < DH; ++d) {
            float4 a  = *(const float4*)&QsT[d][ty * 4];
            float4 bb = *(const float4*)&KsT[d][tx * 4];
            float av[4] = {a.x, a.y, a.z, a.w};
            float bv[4] = {bb.x, bb.y, bb.z, bb.w};
            #pragma unroll
            for (int i = 0; i < 4; ++i)
                #pragma unroll
                for (int j = 0; j < 4; ++j)
                    acc[i][j] += av[i] * bv[j];
        }

        const int4 mk4 = *(const int4*)&mk[tx * 4];
        #pragma unroll
        for (int i = 0; i < 4; ++i) {
            const int qr = ty * 4 + i;
            const bool mrow = (mq[qr] != 0);
            float4 w;
            w.x = (mrow || mk4.x) ? -1000000000.0f : acc[i][0] * 0.125f;
            w.y = (mrow || mk4.y) ? -1000000000.0f : acc[i][1] * 0.125f;
            w.z = (mrow || mk4.z) ? -1000000000.0f : acc[i][2] * 0.125f;
            w.w = (mrow || mk4.w) ? -1000000000.0f : acc[i][3] * 0.125f;
            *(float4*)(arow_base + (size_t)qr * NSEQ + kt * KTILE + tx * 4) = w;
        }
    }
}

__global__ __launch_bounds__(256) void rowstats_kernel(const float* __restrict__ attn)
{
    const int row  = blockIdx.x * 8 + (threadIdx.x >> 5);
    const int lane = threadIdx.x & 31;
    const float* p = attn + (size_t)row * NSEQ;

    float m = -3.4e38f, l = 0.f;
    #pragma unroll 4
    for (int i = 0; i < NSEQ / 128; ++i) {
        float4 vv = *(const float4*)(p + (size_t)(i * 32 + lane) * 4);
        float mloc = fmaxf(fmaxf(vv.x, vv.y), fmaxf(vv.z, vv.w));
        if (mloc > m) { l *= __expf(m - mloc); m = mloc; }
        l += __expf(vv.x - m) + __expf(vv.y - m) +
             __expf(vv.z - m) + __expf(vv.w - m);
    }
    #pragma unroll
    for (int o = 16; o > 0; o >>= 1) {
        float mo = __shfl_xor_sync(0xffffffffu, m, o);
        float lo = __shfl_xor_sync(0xffffffffu, l, o);
        float mn = fmaxf(m, mo);
        l = l * __expf(m - mn) + lo * __expf(mo - mn);
        m = mn;
    }
    if (lane == 0) { g_m[row] = m; g_l[row] = l; }
}

__global__ __launch_bounds__(256) void pv_kernel(
    const float* __restrict__ v, float* __restrict__ attn,
    float* __restrict__ out)
{
    __shared__ float PsT[KTILE][68];   // [k][qrow]
    __shared__ float Vs[KTILE][68];    // [k][d]
    __shared__ float sm[QTILE];
    __shared__ float srl[QTILE];

    const int qt  = blockIdx.x;
    const int bh  = blockIdx.y;
    const int tid = threadIdx.x;
    const int tx  = tid & 15;
    const int ty  = tid >> 4;
    const int r   = tid >> 2;
    const int c0  = (tid & 3) * 16;

    if (tid < QTILE) {
        const int row = bh * NSEQ + qt * QTILE + tid;
        sm[tid]  = g_m[row];
        srl[tid] = 1.f / g_l[row];
    }

    float* arow_base = attn + ((size_t)bh * NSEQ + (size_t)qt * QTILE) * NSEQ;

    float acc[4][4];
    #pragma unroll
    for (int i = 0; i < 4; ++i)
        #pragma unroll
        for (int j = 0; j < 4; ++j) acc[i][j] = 0.f;

    for (int kt = 0; kt < NSEQ / KTILE; ++kt) {
        __syncthreads();
        const float* vbase = v + ((size_t)bh * NSEQ + (size_t)kt * KTILE) * DH;
        #pragma unroll
        for (int c = 0; c < 16; c += 4)
            *(float4*)&Vs[r][c0 + c] = *(const float4*)(vbase + r * DH + c0 + c);

        const float mrow  = sm[r];
        const float rlrow = srl[r];
        float* srow = arow_base + (size_t)r * NSEQ + kt * KTILE + c0;
        #pragma unroll
        for (int c = 0; c < 16; c += 4) {
            float4 s4 = *(const float4*)(srow + c);
            float4 p4;
            p4.x = __expf(s4.x - mrow) * rlrow;
            p4.y = __expf(s4.y - mrow) * rlrow;
            p4.z = __expf(s4.z - mrow) * rlrow;
            p4.w = __expf(s4.w - mrow) * rlrow;
            *(float4*)(srow + c) = p4;           // normalized attn out
            PsT[c0 + c + 0][r] = p4.x;
            PsT[c0 + c + 1][r] = p4.y;
            PsT[c0 + c + 2][r] = p4.z;
            PsT[c0 + c + 3][r] = p4.w;
        }
        __syncthreads();

        #pragma unroll 8
        for (int kk = 0; kk < KTILE; ++kk) {
            float4 a  = *(const float4*)&PsT[kk][ty * 4];
            float4 bb = *(const float4*)&Vs[kk][tx * 4];
            float av[4] = {a.x, a.y, a.z, a.w};
            float bv[4] = {bb.x, bb.y, bb.z, bb.w};
            #pragma unroll
            for (int i = 0; i < 4; ++i)
                #pragma unroll
                for (int j = 0; j < 4; ++j)
                    acc[i][j] += av[i] * bv[j];
        }
    }

    float* obase = out + ((size_t)bh * NSEQ + (size_t)qt * QTILE) * DH;
    #pragma unroll
    for (int i = 0; i < 4; ++i) {
        float4 w = make_float4(acc[i][0], acc[i][1], acc[i][2], acc[i][3]);
        *(float4*)(obase + (size_t)(ty * 4 + i) * DH + tx * 4) = w;
    }
}

extern "C" void kernel_launch(void* const* d_in, const int* in_sizes, int n_in,
                              void* d_out, int out_size)
{
    const float* q    = (const float*)d_in[0];
    const float* k    = (const float*)d_in[1];
    const float* v    = (const float*)d_in[2];
    const int*   mask = (const int*)d_in[3];

    float* out  = (float*)d_out;                       // [B,H,N,D] first (tuple order)
    float* attn = out + (size_t)NBH * NSEQ * DH;       // [B,H,N,N] second

    dim3 grid(NSEQ / QTILE, NBH);
    qk_kernel<<<grid, 256>>>(q, k, mask, attn);
    rowstats_kernel<<<NBH * NSEQ / 8, 256>>>(attn);
    pv_kernel<<<grid, 256>>>(v, attn, out);
}

// round 3
// speedup vs baseline: 1.3041x; 1.3041x over previous
#include <cuda_runtime.h>

#define NSEQ 2048
#define DH   64
#define NBH  32      // B*H

static __device__ float g_l[NBH * NSEQ];

// ---------------------------------------------------------------------------
// qk: E = exp(mask ? -50 : (q.k)/8), fused row-sum into g_l.
// Block tile: 128 q-rows x 128 k-cols, 256 threads, 8x8 microtile.
// K streamed in d-halves so static smem = 32KB + 16KB = 48KB.
// ---------------------------------------------------------------------------
__global__ __launch_bounds__(256) void qk_kernel(
    const float* __restrict__ q, const float* __restrict__ kmat,
    const int* __restrict__ mask, float* __restrict__ attn)
{
    __shared__ float QsT[DH][128];   // [d][qrow]
    __shared__ float KsT[32][128];   // [d-half][krow]

    const int qt  = blockIdx.x;      // 0..15
    const int bh  = blockIdx.y;
    const int b   = bh >> 4;
    const int tid = threadIdx.x;
    const int tx  = tid & 15;        // k cols: tx*4+j, 64+tx*4+j
    const int ty  = tid >> 4;        // q rows: ty*4+i, 64+ty*4+i

    // Load Q tile transposed (128 rows x 64 d)
    const float* qbase = q + ((size_t)bh * NSEQ + (size_t)qt * 128) * DH;
    {
        const int r  = tid >> 1;          // 0..127
        const int c0 = (tid & 1) * 32;
        #pragma unroll
        for (int c = 0; c < 32; c += 4) {
            float4 v4 = *(const float4*)(qbase + r * DH + c0 + c);
            QsT[c0 + c + 0][r] = v4.x;
            QsT[c0 + c + 1][r] = v4.y;
            QsT[c0 + c + 2][r] = v4.z;
            QsT[c0 + c + 3][r] = v4.w;
        }
    }

    // Row-mask bits for this thread's 8 rows
    unsigned mrow_bits = 0;
    #pragma unroll
    for (int i = 0; i < 8; ++i) {
        const int qr = ((i >> 2) * 64) + ty * 4 + (i & 3);
        mrow_bits |= (mask[b * NSEQ + qt * 128 + qr] != 0) ? (1u << i) : 0u;
    }

    float lsum[8];
    #pragma unroll
    for (int i = 0; i < 8; ++i) lsum[i] = 0.f;

    float* abase = attn + ((size_t)bh * NSEQ + (size_t)qt * 128) * NSEQ;

    for (int kt = 0; kt < NSEQ / 128; ++kt) {
        // Col-mask bits for this kt tile (L1/L2-cached broadcast loads)
        unsigned mcol_bits = 0;
        #pragma unroll
        for (int j = 0; j < 8; ++j) {
            const int kc = ((j >> 2) * 64) + tx * 4 + (j & 3);
            mcol_bits |= (mask[b * NSEQ + kt * 128 + kc] != 0) ? (1u << j) : 0u;
        }

        float acc[8][8];
        #pragma unroll
        for (int i = 0; i < 8; ++i)
            #pragma unroll
            for (int j = 0; j < 8; ++j) acc[i][j] = 0.f;

        const float* kbase = kmat + ((size_t)bh * NSEQ + (size_t)kt * 128) * DH;

        #pragma unroll
        for (int dh2 = 0; dh2 < 2; ++dh2) {
            __syncthreads();
            // Load K d-half transposed (128 k-rows x 32 d)
            {
                const int r  = tid >> 1;
                const int c0 = (tid & 1) * 16;
                #pragma unroll
                for (int c = 0; c < 16; c += 4) {
                    float4 v4 = *(const float4*)(kbase + r * DH + dh2 * 32 + c0 + c);
                    KsT[c0 + c + 0][r] = v4.x;
                    KsT[c0 + c + 1][r] = v4.y;
                    KsT[c0 + c + 2][r] = v4.z;
                    KsT[c0 + c + 3][r] = v4.w;
                }
            }
            __syncthreads();

            #pragma unroll 8
            for (int d = 0; d < 32; ++d) {
                float4 q0 = *(const float4*)&QsT[dh2 * 32 + d][ty * 4];
                float4 q1 = *(const float4*)&QsT[dh2 * 32 + d][64 + ty * 4];
                float4 k0 = *(const float4*)&KsT[d][tx * 4];
                float4 k1 = *(const float4*)&KsT[d][64 + tx * 4];
                float av[8] = {q0.x, q0.y, q0.z, q0.w, q1.x, q1.y, q1.z, q1.w};
                float bv[8] = {k0.x, k0.y, k0.z, k0.w, k1.x, k1.y, k1.z, k1.w};
                #pragma unroll
                for (int i = 0; i < 8; ++i)
                    #pragma unroll
                    for (int j = 0; j < 8; ++j)
                        acc[i][j] += av[i] * bv[j];
            }
        }

        // mask + exp + store E + accumulate row sums
        #pragma unroll
        for (int i = 0; i < 8; ++i) {
            const int  qr   = ((i >> 2) * 64) + ty * 4 + (i & 3);
            const bool mr   = (mrow_bits >> i) & 1u;
            float e[8];
            #pragma unroll
            for (int j = 0; j < 8; ++j) {
                const bool mm = mr || ((mcol_bits >> j) & 1u);
                const float s = mm ? -50.f : acc[i][j] * 0.125f;
                e[j] = __expf(s);
                lsum[i] += e[j];
            }
            float* dst = abase + (size_t)qr * NSEQ + kt * 128;
            *(float4*)(dst + tx * 4)      = make_float4(e[0], e[1], e[2], e[3]);
            *(float4*)(dst + 64 + tx * 4) = make_float4(e[4], e[5], e[6], e[7]);
        }
    }

    // Reduce row sums across the 16 tx-lanes (xor<16 stays in half-warp = same ty)
    #pragma unroll
    for (int i = 0; i < 8; ++i) {
        float s2 = lsum[i];
        s2 += __shfl_xor_sync(0xffffffffu, s2, 1);
        s2 += __shfl_xor_sync(0xffffffffu, s2, 2);
        s2 += __shfl_xor_sync(0xffffffffu, s2, 4);
        s2 += __shfl_xor_sync(0xffffffffu, s2, 8);
        lsum[i] = s2;
    }
    if (tx == 0) {
        #pragma unroll
        for (int i = 0; i < 8; ++i) {
            const int qr = ((i >> 2) * 64) + ty * 4 + (i & 3);
            g_l[bh * NSEQ + qt * 128 + qr] = lsum[i];
        }
    }
}

// ---------------------------------------------------------------------------
// pv: p = E / l (written back as the attn output), O = P.V
// Block tile: 256 q-rows x 64 d-cols, 256 threads, 8x8 microtile, KTILE=32.
// ---------------------------------------------------------------------------
__global__ __launch_bounds__(256) void pv_kernel(
    const float* __restrict__ v, float* __restrict__ attn,
    float* __restrict__ out)
{
    __shared__ float Ps[256 * 36];   // [row][k] stride 36
    __shared__ float Vs[32 * 68];    // [k][d]   stride 68
    __shared__ float rl[256];

    const int qt  = blockIdx.x;      // 0..7
    const int bh  = blockIdx.y;
    const int tid = threadIdx.x;
    const int tx  = tid & 7;         // d cols: tx*4+j, 32+tx*4+j
    const int ty  = tid >> 3;        // q rows: ty*4+i, 128+ty*4+i

    rl[tid] = 1.f / g_l[bh * NSEQ + qt * 256 + tid];

    float* abase = attn + ((size_t)bh * NSEQ + (size_t)qt * 256) * NSEQ;
    const float* vbase = v + (size_t)bh * NSEQ * DH;

    float acc[8][8];
    #pragma unroll
    for (int i = 0; i < 8; ++i)
        #pragma unroll
        for (int j = 0; j < 8; ++j) acc[i][j] = 0.f;

    for (int kt = 0; kt < NSEQ / 32; ++kt) {
        __syncthreads();
        // V tile: 32 k-rows x 64 d
        {
            const int r = tid >> 3;
            const int c = (tid & 7) * 8;
            float4 a4 = *(const float4*)(vbase + (size_t)(kt * 32 + r) * DH + c);
            float4 b4 = *(const float4*)(vbase + (size_t)(kt * 32 + r) * DH + c + 4);
            *(float4*)&Vs[r * 68 + c]     = a4;
            *(float4*)&Vs[r * 68 + c + 4] = b4;
        }
        // E tile: 256 rows x 32 cols -> normalize, write attn, stage in smem
        {
            const int c  = (tid & 7) * 4;
            const int r0 = tid >> 3;
            #pragma unroll
            for (int i = 0; i < 8; ++i) {
                const int r = r0 + 32 * i;
                float* ap = abase + (size_t)r * NSEQ + kt * 32 + c;
                float4 e4 = *(const float4*)ap;
                const float s = rl[r];
                float4 p4 = make_float4(e4.x * s, e4.y * s, e4.z * s, e4.w * s);
                *(float4*)ap = p4;                 // normalized attn output
                *(float4*)&Ps[r * 36 + c] = p4;
            }
        }
        __syncthreads();

        #pragma unroll
        for (int k0 = 0; k0 < 32; k0 += 4) {
            float Pfa[8][4];
            #pragma unroll
            for (int i = 0; i < 8; ++i) {
                const int r = ((i >> 2) * 128) + ty * 4 + (i & 3);
                float4 t = *(const float4*)&Ps[r * 36 + k0];
                Pfa[i][0] = t.x; Pfa[i][1] = t.y; Pfa[i][2] = t.z; Pfa[i][3] = t.w;
            }
            #pragma unroll
            for (int kk = 0; kk < 4; ++kk) {
                float4 v0 = *(const float4*)&Vs[(k0 + kk) * 68 + tx * 4];
                float4 v1 = *(const float4*)&Vs[(k0 + kk) * 68 + 32 + tx * 4];
                float bv[8] = {v0.x, v0.y, v0.z, v0.w, v1.x, v1.y, v1.z, v1.w};
                #pragma unroll
                for (int i = 0; i < 8; ++i)
                    #pragma unroll
                    for (int j = 0; j < 8; ++j)
                        acc[i][j] += Pfa[i][kk] * bv[j];
            }
        }
    }

    float* obase = out + ((size_t)bh * NSEQ + (size_t)qt * 256) * DH;
    #pragma unroll
    for (int i = 0; i < 8; ++i) {
        const int row = ((i >> 2) * 128) + ty * 4 + (i & 3);
        *(float4*)(obase + (size_t)row * DH + tx * 4)
            = make_float4(acc[i][0], acc[i][1], acc[i][2], acc[i][3]);
        *(float4*)(obase + (size_t)row * DH + 32 + tx * 4)
            = make_float4(acc[i][4], acc[i][5], acc[i][6], acc[i][7]);
    }
}

extern "C" void kernel_launch(void* const* d_in, const int* in_sizes, int n_in,
                              void* d_out, int out_size)
{
    const float* q    = (const float*)d_in[0];
    const float* kmat = (const float*)d_in[1];
    const float* v    = (const float*)d_in[2];
    const int*   mask = (const int*)d_in[3];

    float* out  = (float*)d_out;                  // [B,H,N,D] first (tuple order)
    float* attn = out + (size_t)NBH * NSEQ * DH;  // [B,H,N,N] second

    qk_kernel<<<dim3(NSEQ / 128, NBH), 256>>>(q, kmat, mask, attn);
    pv_kernel<<<dim3(NSEQ / 256, NBH), 256>>>(v, attn, out);
}

// round 4
// speedup vs baseline: 1.4348x; 1.1003x over previous
#include <cuda_runtime.h>

#define NSEQ 2048
#define DH   64
#define NBH  32      // B*H

static __device__ float g_l[NBH * NSEQ];

// ---------------------------------------------------------------------------
// qk: E = exp(mask ? -50 : (q.k)/8), fused row-sum into g_l.
// Block tile: 128 q-rows x 128 k-cols, 256 threads, 8x8 microtile.
// K streamed in d-halves (regs-prefetched), smem = 32KB + 16KB = 48KB.
// ---------------------------------------------------------------------------
__global__ __launch_bounds__(256) void qk_kernel(
    const float* __restrict__ q, const float* __restrict__ kmat,
    const int* __restrict__ mask, float* __restrict__ attn)
{
    __shared__ float QsT[DH][128];   // [d][qrow]
    __shared__ float KsT[32][128];   // [d-half][krow]

    const int qt  = blockIdx.x;      // 0..15
    const int bh  = blockIdx.y;
    const int b   = bh >> 4;
    const int tid = threadIdx.x;
    const int tx  = tid & 15;        // k cols: tx*4+j, 64+tx*4+j
    const int ty  = tid >> 4;        // q rows: ty*4+i, 64+ty*4+i

    // Load Q tile transposed (128 rows x 64 d)
    const float* qbase = q + ((size_t)bh * NSEQ + (size_t)qt * 128) * DH;
    {
        const int r  = tid >> 1;          // 0..127
        const int c0 = (tid & 1) * 32;
        #pragma unroll
        for (int c = 0; c < 32; c += 4) {
            float4 v4 = *(const float4*)(qbase + r * DH + c0 + c);
            QsT[c0 + c + 0][r] = v4.x;
            QsT[c0 + c + 1][r] = v4.y;
            QsT[c0 + c + 2][r] = v4.z;
            QsT[c0 + c + 3][r] = v4.w;
        }
    }

    // Row-mask bits for this thread's 8 rows
    unsigned mrow_bits = 0;
    #pragma unroll
    for (int i = 0; i < 8; ++i) {
        const int qr = ((i >> 2) * 64) + ty * 4 + (i & 3);
        mrow_bits |= (mask[b * NSEQ + qt * 128 + qr] != 0) ? (1u << i) : 0u;
    }

    float lsum[8];
    #pragma unroll
    for (int i = 0; i < 8; ++i) lsum[i] = 0.f;

    float* abase = attn + ((size_t)bh * NSEQ + (size_t)qt * 128) * NSEQ;
    const float* kball = kmat + (size_t)bh * NSEQ * DH;

    // K-tile register staging: r = tid>>1 (0..127), c0 = (tid&1)*16
    const int kr  = tid >> 1;
    const int kc0 = (tid & 1) * 16;
    float4 kReg[4];
    #pragma unroll
    for (int c = 0; c < 4; ++c)
        kReg[c] = *(const float4*)(kball + (size_t)kr * DH + kc0 + 4 * c);

    for (int kt = 0; kt < NSEQ / 128; ++kt) {
        // Col-mask bits for this kt tile (L1-cached broadcast loads)
        unsigned mcol_bits = 0;
        #pragma unroll
        for (int j = 0; j < 8; ++j) {
            const int kc = ((j >> 2) * 64) + tx * 4 + (j & 3);
            mcol_bits |= (mask[b * NSEQ + kt * 128 + kc] != 0) ? (1u << j) : 0u;
        }

        float acc[8][8];
        #pragma unroll
        for (int i = 0; i < 8; ++i)
            #pragma unroll
            for (int j = 0; j < 8; ++j) acc[i][j] = 0.f;

        #pragma unroll
        for (int dh2 = 0; dh2 < 2; ++dh2) {
            __syncthreads();
            // Commit staged K d-half (transposed) to smem
            #pragma unroll
            for (int c = 0; c < 4; ++c) {
                KsT[kc0 + 4 * c + 0][kr] = kReg[c].x;
                KsT[kc0 + 4 * c + 1][kr] = kReg[c].y;
                KsT[kc0 + 4 * c + 2][kr] = kReg[c].z;
                KsT[kc0 + 4 * c + 3][kr] = kReg[c].w;
            }
            __syncthreads();

            // Prefetch next K d-half into registers (overlaps with GEMM below)
            {
                const int nkt = kt + dh2;        // (kt,0)->(kt,1), (kt,1)->(kt+1,0)
                const int ndh = dh2 ^ 1;
                if (nkt < NSEQ / 128) {
                    const float* kb = kball + (size_t)(nkt * 128 + kr) * DH + ndh * 32 + kc0;
                    #pragma unroll
                    for (int c = 0; c < 4; ++c)
                        kReg[c] = *(const float4*)(kb + 4 * c);
                }
            }

            #pragma unroll 8
            for (int d = 0; d < 32; ++d) {
                float4 q0 = *(const float4*)&QsT[dh2 * 32 + d][ty * 4];
                float4 q1 = *(const float4*)&QsT[dh2 * 32 + d][64 + ty * 4];
                float4 k0 = *(const float4*)&KsT[d][tx * 4];
                float4 k1 = *(const float4*)&KsT[d][64 + tx * 4];
                float av[8] = {q0.x, q0.y, q0.z, q0.w, q1.x, q1.y, q1.z, q1.w};
                float bv[8] = {k0.x, k0.y, k0.z, k0.w, k1.x, k1.y, k1.z, k1.w};
                #pragma unroll
                for (int i = 0; i < 8; ++i)
                    #pragma unroll
                    for (int j = 0; j < 8; ++j)
                        acc[i][j] += av[i] * bv[j];
            }
        }

        // mask + exp + store E + accumulate row sums
        #pragma unroll
        for (int i = 0; i < 8; ++i) {
            const int  qr = ((i >> 2) * 64) + ty * 4 + (i & 3);
            const bool mr = (mrow_bits >> i) & 1u;
            float e[8];
            #pragma unroll
            for (int j = 0; j < 8; ++j) {
                const bool mm = mr || ((mcol_bits >> j) & 1u);
                const float s = mm ? -50.f : acc[i][j] * 0.125f;
                e[j] = __expf(s);
                lsum[i] += e[j];
            }
            float* dst = abase + (size_t)qr * NSEQ + kt * 128;
            *(float4*)(dst + tx * 4)      = make_float4(e[0], e[1], e[2], e[3]);
            *(float4*)(dst + 64 + tx * 4) = make_float4(e[4], e[5], e[6], e[7]);
        }
    }

    // Reduce row sums across the 16 tx-lanes (xor<16 stays in half-warp)
    #pragma unroll
    for (int i = 0; i < 8; ++i) {
        float s2 = lsum[i];
        s2 += __shfl_xor_sync(0xffffffffu, s2, 1);
        s2 += __shfl_xor_sync(0xffffffffu, s2, 2);
        s2 += __shfl_xor_sync(0xffffffffu, s2, 4);
        s2 += __shfl_xor_sync(0xffffffffu, s2, 8);
        lsum[i] = s2;
    }
    if (tx == 0) {
        #pragma unroll
        for (int i = 0; i < 8; ++i) {
            const int qr = ((i >> 2) * 64) + ty * 4 + (i & 3);
            g_l[bh * NSEQ + qt * 128 + qr] = lsum[i];
        }
    }
}

// ---------------------------------------------------------------------------
// pv: p = E / l (written back as the attn output), O = P.V
// Block tile: 128 q-rows x 64 d-cols, 128 threads, 8x8 microtile, KTILE=32.
// Register double-buffering of the E/V tiles; smem ~27KB -> 3-4 CTAs/SM.
// ---------------------------------------------------------------------------
__global__ __launch_bounds__(128) void pv_kernel(
    const float* __restrict__ v, float* __restrict__ attn,
    float* __restrict__ out)
{
    __shared__ float Ps[128 * 36];   // [row][k] stride 36
    __shared__ float Vs[32 * 68];    // [k][d]   stride 68

    const int qt  = blockIdx.x;      // 0..15
    const int bh  = blockIdx.y;
    const int tid = threadIdx.x;
    const int tx  = tid & 7;         // d cols: tx*4+j, 32+tx*4+j
    const int ty  = tid >> 3;        // q rows: ty*4+(i&3) + 64*(i>>2)

    // staging indices
    const int sc  = (tid & 7) * 4;   // E col within 32-wide tile
    const int sr0 = tid >> 3;        // E row base (stride 16)
    const int vr  = tid >> 2;        // V row 0..31
    const int vc  = (tid & 3) * 16;  // V col base

    float rlv[8];
    #pragma unroll
    for (int i = 0; i < 8; ++i)
        rlv[i] = 1.f / g_l[bh * NSEQ + qt * 128 + sr0 + 16 * i];

    float* abase = attn + ((size_t)bh * NSEQ + (size_t)qt * 128) * NSEQ;
    const float* vbase = v + (size_t)bh * NSEQ * DH;

    // Prefetch tile kt=0 into registers
    float4 eReg[8];
    float4 vReg[4];
    #pragma unroll
    for (int i = 0; i < 8; ++i)
        eReg[i] = *(const float4*)(abase + (size_t)(sr0 + 16 * i) * NSEQ + sc);
    #pragma unroll
    for (int j = 0; j < 4; ++j)
        vReg[j] = *(const float4*)(vbase + (size_t)vr * DH + vc + 4 * j);

    float acc[8][8];
    #pragma unroll
    for (int i = 0; i < 8; ++i)
        #pragma unroll
        for (int j = 0; j < 8; ++j) acc[i][j] = 0.f;

    for (int kt = 0; kt < NSEQ / 32; ++kt) {
        __syncthreads();   // previous GEMM done consuming smem
        // Commit staged tile: normalize E, write P to gmem + smem; V to smem
        #pragma unroll
        for (int i = 0; i < 8; ++i) {
            const int r = sr0 + 16 * i;
            const float s = rlv[i];
            float4 p4 = make_float4(eReg[i].x * s, eReg[i].y * s,
                                    eReg[i].z * s, eReg[i].w * s);
            *(float4*)(abase + (size_t)r * NSEQ + kt * 32 + sc) = p4;
            *(float4*)&Ps[r * 36 + sc] = p4;
        }
        #pragma unroll
        for (int j = 0; j < 4; ++j)
            *(float4*)&Vs[vr * 68 + vc + 4 * j] = vReg[j];
        __syncthreads();

        // Prefetch next tile (overlaps with GEMM below)
        if (kt + 1 < NSEQ / 32) {
            const float* ebp = abase + (kt + 1) * 32 + sc;
            #pragma unroll
            for (int i = 0; i < 8; ++i)
                eReg[i] = *(const float4*)(ebp + (size_t)(sr0 + 16 * i) * NSEQ);
            const float* vbp = vbase + (size_t)((kt + 1) * 32 + vr) * DH + vc;
            #pragma unroll
            for (int j = 0; j < 4; ++j)
                vReg[j] = *(const float4*)(vbp + 4 * j);
        }

        // GEMM: 32 k-steps
        #pragma unroll
        for (int k0 = 0; k0 < 32; k0 += 4) {
            float Pfa[8][4];
            #pragma unroll
            for (int i = 0; i < 8; ++i) {
                const int r = ((i >> 2) * 64) + ty * 4 + (i & 3);
                float4 t = *(const float4*)&Ps[r * 36 + k0];
                Pfa[i][0] = t.x; Pfa[i][1] = t.y; Pfa[i][2] = t.z; Pfa[i][3] = t.w;
            }
            #pragma unroll
            for (int kk = 0; kk < 4; ++kk) {
                float4 v0 = *(const float4*)&Vs[(k0 + kk) * 68 + tx * 4];
                float4 v1 = *(const float4*)&Vs[(k0 + kk) * 68 + 32 + tx * 4];
                float bv[8] = {v0.x, v0.y, v0.z, v0.w, v1.x, v1.y, v1.z, v1.w};
                #pragma unroll
                for (int i = 0; i < 8; ++i)
                    #pragma unroll
                    for (int j = 0; j < 8; ++j)
                        acc[i][j] += Pfa[i][kk] * bv[j];
            }
        }
    }

    float* obase = out + ((size_t)bh * NSEQ + (size_t)qt * 128) * DH;
    #pragma unroll
    for (int i = 0; i < 8; ++i) {
        const int row = ((i >> 2) * 64) + ty * 4 + (i & 3);
        *(float4*)(obase + (size_t)row * DH + tx * 4)
            = make_float4(acc[i][0], acc[i][1], acc[i][2], acc[i][3]);
        *(float4*)(obase + (size_t)row * DH + 32 + tx * 4)
            = make_float4(acc[i][4], acc[i][5], acc[i][6], acc[i][7]);
    }
}

extern "C" void kernel_launch(void* const* d_in, const int* in_sizes, int n_in,
                              void* d_out, int out_size)
{
    const float* q    = (const float*)d_in[0];
    const float* kmat = (const float*)d_in[1];
    const float* v    = (const float*)d_in[2];
    const int*   mask = (const int*)d_in[3];

    float* out  = (float*)d_out;                  // [B,H,N,D] first (tuple order)
    float* attn = out + (size_t)NBH * NSEQ * DH;  // [B,H,N,N] second

    qk_kernel<<<dim3(NSEQ / 128, NBH), 256>>>(q, kmat, mask, attn);
    pv_kernel<<<dim3(NSEQ / 128, NBH), 128>>>(v, attn, out);
}